// round 6
// baseline (speedup 1.0000x reference)
#include <cuda_runtime.h>
#include <cmath>

// Problem shapes (fixed per reference)
#define B_   32
#define S_   4096
#define QD   512
#define KVD  512

// k2 grid: 444 CTAs = 3 per SM on 148 SMs (single wave at occupancy 3).
// First 28 batches get 14 chunks, last 4 batches get 13 chunks. 28*14+4*13=444.
#define NB14     28
#define MAXNC    14

// Scratch (device globals; no allocation allowed)
__device__ float g_wq[B_ * KVD];                  // final W^T q   (64 KB)
__device__ float g_pm[B_ * MAXNC];
__device__ float g_pl[B_ * MAXNC];
__device__ float g_pacc[B_ * MAXNC * KVD];        // ~917 KB

// ---------------------------------------------------------------------------
// Kernel 1: wq[b,k] = sum_q W[q][k] * query[b][q].
// grid(64): block kb owns 8 k-columns for ALL 32 batches -> W read exactly once.
// thread t: k = kb*8 + (t&7), b = t>>3  (one output element per thread).
// ---------------------------------------------------------------------------
__global__ void __launch_bounds__(256) k1_wq(const float* __restrict__ query,
                                             const float* __restrict__ weight) {
    __shared__ float sq[B_][129];     // padded: b-stride 129 -> conflict-free
    __shared__ float sW[128][8];

    const int t  = threadIdx.x;
    const int kb = blockIdx.x;        // 0..63
    const int k  = t & 7;
    const int b  = t >> 3;

    float a0 = 0.f, a1 = 0.f, a2 = 0.f, a3 = 0.f;

    for (int qc = 0; qc < QD; qc += 128) {
        __syncthreads();
        // stage query chunk [32][128]
        for (int i = t; i < B_ * 128; i += 256)
            sq[i >> 7][i & 127] = query[(i >> 7) * QD + qc + (i & 127)];
        // stage W chunk [128][8]
        for (int i = t; i < 128 * 8; i += 256)
            sW[i >> 3][i & 7] = weight[(size_t)(qc + (i >> 3)) * KVD + kb * 8 + (i & 7)];
        __syncthreads();

#pragma unroll
        for (int q = 0; q < 128; q += 4) {
            a0 += sW[q + 0][k] * sq[b][q + 0];
            a1 += sW[q + 1][k] * sq[b][q + 1];
            a2 += sW[q + 2][k] * sq[b][q + 2];
            a3 += sW[q + 3][k] * sq[b][q + 3];
        }
    }
    g_wq[b * KVD + kb * 8 + k] = (a0 + a1) + (a2 + a3);
}

// ---------------------------------------------------------------------------
// Kernel 2: fused masked-score + online softmax + weighted sum over a chunk.
// grid(444), 256 threads (8 warps). Warp-per-row; lane owns 16 k-values.
// ---------------------------------------------------------------------------
__global__ void __launch_bounds__(256, 3) k2_fused(const float* __restrict__ kv,
                                                   const int*   __restrict__ mask) {
    const int id  = blockIdx.x;
    int b, c, n;
    if (id < NB14 * 14) { b = id / 14; c = id % 14; n = 14; }
    else { const int r = id - NB14 * 14; b = NB14 + r / 13; c = r % 13; n = 13; }

    const int base  = S_ / n;
    const int rem   = S_ % n;
    const int start = c * base + min(c, rem);
    const int R     = base + (c < rem ? 1 : 0);   // rows in this chunk (292..316)

    const int tid  = threadIdx.x;
    const int w    = tid >> 5;
    const int lane = tid & 31;

    __shared__ float s_m[8];
    __shared__ float s_l[8];
    __shared__ float s_acc[8][KVD];   // 16 KB

    // wq straight from global (L1/L2 resident, written once by k1)
    float4 wqr[4];
    {
        const float4* wq4 = (const float4*)(g_wq + b * KVD);
#pragma unroll
        for (int j = 0; j < 4; ++j) wqr[j] = wq4[j * 32 + lane];
    }

    const size_t rowbase = ((size_t)b * S_ + (size_t)start);
    const float4* kv4 = (const float4*)(kv + rowbase * KVD);
    const int*    mb  = mask + rowbase;

    float m = -1e30f, l = 0.f;
    float4 acc[4];
#pragma unroll
    for (int j = 0; j < 4; ++j) acc[j] = make_float4(0.f, 0.f, 0.f, 0.f);

    float4 cur[4], nxt[4];
    int curmask = 0, nxtmask = 0;

    int r = w;
    if (r < R) {
        const float4* rp = kv4 + (size_t)r * (KVD / 4);
#pragma unroll
        for (int j = 0; j < 4; ++j) cur[j] = rp[j * 32 + lane];
        curmask = mb[r];
    }

    while (r < R) {
        const int rn = r + 8;
        if (rn < R) {   // prefetch next row (uniform branch within warp)
            const float4* rp = kv4 + (size_t)rn * (KVD / 4);
#pragma unroll
            for (int j = 0; j < 4; ++j) nxt[j] = rp[j * 32 + lane];
            nxtmask = mb[rn];
        }

        // dot(kv_row, wq)
        float d = 0.f;
#pragma unroll
        for (int j = 0; j < 4; ++j) {
            d += cur[j].x * wqr[j].x;
            d += cur[j].y * wqr[j].y;
            d += cur[j].z * wqr[j].z;
            d += cur[j].w * wqr[j].w;
        }
#pragma unroll
        for (int off = 16; off > 0; off >>= 1)
            d += __shfl_xor_sync(0xFFFFFFFFu, d, off);

        const bool  valid = (curmask != 0);
        const float dv    = valid ? d : -1e30f;
        const float mnew  = fmaxf(m, dv);
        const float alpha = __expf(m - mnew);          // ==1 when m unchanged
        const float p     = valid ? __expf(d - mnew) : 0.f;

        l = l * alpha + p;
#pragma unroll
        for (int j = 0; j < 4; ++j) {
            acc[j].x = acc[j].x * alpha + p * cur[j].x;
            acc[j].y = acc[j].y * alpha + p * cur[j].y;
            acc[j].z = acc[j].z * alpha + p * cur[j].z;
            acc[j].w = acc[j].w * alpha + p * cur[j].w;
        }
        m = mnew;

#pragma unroll
        for (int j = 0; j < 4; ++j) cur[j] = nxt[j];
        curmask = nxtmask;
        r = rn;
    }

    // --- block combine across 8 warps ---
    if (lane == 0) { s_m[w] = m; s_l[w] = l; }
    float4* srow = (float4*)s_acc[w];
#pragma unroll
    for (int j = 0; j < 4; ++j) srow[j * 32 + lane] = acc[j];
    __syncthreads();

    float mblk = -1e30f;
#pragma unroll
    for (int w2 = 0; w2 < 8; ++w2) mblk = fmaxf(mblk, s_m[w2]);
    float f[8];
    float lblk = 0.f;
#pragma unroll
    for (int w2 = 0; w2 < 8; ++w2) {
        f[w2] = __expf(s_m[w2] - mblk);
        lblk += f[w2] * s_l[w2];
    }

    const size_t pbase = ((size_t)b * MAXNC + c) * KVD;
    for (int k = tid; k < KVD; k += 256) {
        float v = 0.f;
#pragma unroll
        for (int w2 = 0; w2 < 8; ++w2) v += f[w2] * s_acc[w2][k];
        g_pacc[pbase + k] = v;
    }
    if (tid == 0) { g_pm[b * MAXNC + c] = mblk; g_pl[b * MAXNC + c] = lblk; }
}

// ---------------------------------------------------------------------------
// Kernel 3: combine chunk partials.  grid(B), 256 threads (k and k+256).
// ---------------------------------------------------------------------------
__global__ void __launch_bounds__(256) k3_combine(float* __restrict__ out) {
    const int b   = blockIdx.x;
    const int tid = threadIdx.x;
    const int n   = (b < NB14) ? 14 : 13;

    __shared__ float spm[MAXNC], spl[MAXNC];
    if (tid < n) { spm[tid] = g_pm[b * MAXNC + tid]; spl[tid] = g_pl[b * MAXNC + tid]; }
    __syncthreads();

    float mstar = -1e30f;
    for (int cc = 0; cc < n; ++cc) mstar = fmaxf(mstar, spm[cc]);

    float denom = 0.f, n0 = 0.f, n1 = 0.f;
    for (int cc = 0; cc < n; ++cc) {
        const float fc = __expf(spm[cc] - mstar);
        denom += fc * spl[cc];
        const size_t pbase = ((size_t)b * MAXNC + cc) * KVD;
        n0 += fc * g_pacc[pbase + tid];
        n1 += fc * g_pacc[pbase + tid + 256];
    }
    out[b * KVD + tid]       = n0 / denom;
    out[b * KVD + tid + 256] = n1 / denom;
}

// ---------------------------------------------------------------------------
extern "C" void kernel_launch(void* const* d_in, const int* in_sizes, int n_in,
                              void* d_out, int out_size) {
    const float* query  = (const float*)d_in[0];   // [32, 512]
    const float* kv     = (const float*)d_in[1];   // [32, 4096, 512]
    const int*   mask   = (const int*)  d_in[2];   // [32, 4096]
    const float* weight = (const float*)d_in[3];   // [512, 512]
    float* out = (float*)d_out;                    // [32, 512]

    (void)in_sizes; (void)n_in; (void)out_size;

    k1_wq<<<64, 256>>>(query, weight);
    k2_fused<<<444, 256>>>(kv, mask);
    k3_combine<<<B_, 256>>>(out);
}

// round 10
// speedup vs baseline: 1.7085x; 1.7085x over previous
#include <cuda_runtime.h>
#include <cmath>

// Problem shapes (fixed per reference)
#define B_   32
#define S_   4096
#define QD   512
#define KVD  512

// k2 grid: 444 CTAs = 3 per SM on 148 SMs (single wave at occupancy 3).
// First 28 batches get 14 chunks, last 4 batches get 13 chunks. 28*14+4*13=444.
#define NB14     28
#define MAXNC    14

// k1: 16 q-slices of 32
#define QSLICES  16
#define QS_LEN   (QD / QSLICES)   // 32

// Scratch (device globals; no allocation allowed)
__device__ float g_wqp[QSLICES * B_ * KVD];       // partial W^T q (1 MB)
__device__ float g_wq[B_ * KVD];                  // final W^T q   (64 KB)
__device__ float g_pm[B_ * MAXNC];
__device__ float g_pl[B_ * MAXNC];
__device__ float g_pacc[B_ * MAXNC * KVD];        // ~917 KB

// ---------------------------------------------------------------------------
// Kernel 1: partial wq over a 32-long q-slice.
// grid(QSLICES, B) = 512 CTAs, 256 threads; thread t owns k = t and t+256.
// 64 independent coalesced loads per thread -> high MLP, latency hidden.
// ---------------------------------------------------------------------------
__global__ void __launch_bounds__(256) k1_wq(const float* __restrict__ query,
                                             const float* __restrict__ weight) {
    const int qs = blockIdx.x;
    const int b  = blockIdx.y;
    const int t  = threadIdx.x;

    __shared__ float sq[QS_LEN];
    if (t < QS_LEN) sq[t] = query[b * QD + qs * QS_LEN + t];
    __syncthreads();

    const float* Wp = weight + (size_t)(qs * QS_LEN) * KVD + t;
    float s0 = 0.f, s1 = 0.f;
#pragma unroll
    for (int q = 0; q < QS_LEN; ++q) {
        const float qv = sq[q];
        s0 += qv * Wp[(size_t)q * KVD];
        s1 += qv * Wp[(size_t)q * KVD + 256];
    }
    float* dst = g_wqp + ((size_t)qs * B_ + b) * KVD;
    dst[t]       = s0;
    dst[t + 256] = s1;
}

// ---------------------------------------------------------------------------
// Kernel 1r: reduce the 16 q-slice partials -> g_wq.
// grid(64), 256 threads: block owns half the k-range of one batch.
// ---------------------------------------------------------------------------
__global__ void __launch_bounds__(256) k1r_reduce() {
    const int b = blockIdx.x >> 1;
    const int k = (blockIdx.x & 1) * 256 + threadIdx.x;
    float s = 0.f;
#pragma unroll
    for (int qs = 0; qs < QSLICES; ++qs)
        s += g_wqp[((size_t)qs * B_ + b) * KVD + k];
    g_wq[b * KVD + k] = s;
}

// ---------------------------------------------------------------------------
// Kernel 2: fused masked-score + online softmax + weighted sum over a chunk.
// grid(444), 256 threads (8 warps). Warp-per-row; lane owns 16 k-values.
// ---------------------------------------------------------------------------
__global__ void __launch_bounds__(256, 3) k2_fused(const float* __restrict__ kv,
                                                   const int*   __restrict__ mask) {
    const int id  = blockIdx.x;
    int b, c, n;
    if (id < NB14 * 14) { b = id / 14; c = id % 14; n = 14; }
    else { const int r = id - NB14 * 14; b = NB14 + r / 13; c = r % 13; n = 13; }

    const int base  = S_ / n;
    const int rem   = S_ % n;
    const int start = c * base + min(c, rem);
    const int R     = base + (c < rem ? 1 : 0);   // rows in this chunk

    const int tid  = threadIdx.x;
    const int w    = tid >> 5;
    const int lane = tid & 31;

    __shared__ float s_m[8];
    __shared__ float s_l[8];
    __shared__ float s_acc[8][KVD];   // 16 KB

    // wq straight from global (L2 resident, written once by k1r)
    float4 wqr[4];
    {
        const float4* wq4 = (const float4*)(g_wq + b * KVD);
#pragma unroll
        for (int j = 0; j < 4; ++j) wqr[j] = wq4[j * 32 + lane];
    }

    const size_t rowbase = ((size_t)b * S_ + (size_t)start);
    const float4* kv4 = (const float4*)(kv + rowbase * KVD);
    const int*    mb  = mask + rowbase;

    float m = -1e30f, l = 0.f;
    float4 acc[4];
#pragma unroll
    for (int j = 0; j < 4; ++j) acc[j] = make_float4(0.f, 0.f, 0.f, 0.f);

    float4 cur[4], nxt[4];
    int curmask = 0, nxtmask = 0;

    int r = w;
    if (r < R) {
        const float4* rp = kv4 + (size_t)r * (KVD / 4);
#pragma unroll
        for (int j = 0; j < 4; ++j) cur[j] = rp[j * 32 + lane];
        curmask = mb[r];
    }

    while (r < R) {
        const int rn = r + 8;
        if (rn < R) {   // prefetch next row (uniform branch within warp)
            const float4* rp = kv4 + (size_t)rn * (KVD / 4);
#pragma unroll
            for (int j = 0; j < 4; ++j) nxt[j] = rp[j * 32 + lane];
            nxtmask = mb[rn];
        }

        // dot(kv_row, wq)
        float d = 0.f;
#pragma unroll
        for (int j = 0; j < 4; ++j) {
            d += cur[j].x * wqr[j].x;
            d += cur[j].y * wqr[j].y;
            d += cur[j].z * wqr[j].z;
            d += cur[j].w * wqr[j].w;
        }
#pragma unroll
        for (int off = 16; off > 0; off >>= 1)
            d += __shfl_xor_sync(0xFFFFFFFFu, d, off);

        const bool  valid = (curmask != 0);
        const float dv    = valid ? d : -1e30f;
        const float mnew  = fmaxf(m, dv);
        const float alpha = __expf(m - mnew);          // ==1 when m unchanged
        const float p     = valid ? __expf(d - mnew) : 0.f;

        l = l * alpha + p;
#pragma unroll
        for (int j = 0; j < 4; ++j) {
            acc[j].x = acc[j].x * alpha + p * cur[j].x;
            acc[j].y = acc[j].y * alpha + p * cur[j].y;
            acc[j].z = acc[j].z * alpha + p * cur[j].z;
            acc[j].w = acc[j].w * alpha + p * cur[j].w;
        }
        m = mnew;

#pragma unroll
        for (int j = 0; j < 4; ++j) cur[j] = nxt[j];
        curmask = nxtmask;
        r = rn;
    }

    // --- block combine across 8 warps ---
    if (lane == 0) { s_m[w] = m; s_l[w] = l; }
    float4* srow = (float4*)s_acc[w];
#pragma unroll
    for (int j = 0; j < 4; ++j) srow[j * 32 + lane] = acc[j];
    __syncthreads();

    float mblk = -1e30f;
#pragma unroll
    for (int w2 = 0; w2 < 8; ++w2) mblk = fmaxf(mblk, s_m[w2]);
    float f[8];
    float lblk = 0.f;
#pragma unroll
    for (int w2 = 0; w2 < 8; ++w2) {
        f[w2] = __expf(s_m[w2] - mblk);
        lblk += f[w2] * s_l[w2];
    }

    const size_t pbase = ((size_t)b * MAXNC + c) * KVD;
    for (int k = tid; k < KVD; k += 256) {
        float v = 0.f;
#pragma unroll
        for (int w2 = 0; w2 < 8; ++w2) v += f[w2] * s_acc[w2][k];
        g_pacc[pbase + k] = v;
    }
    if (tid == 0) { g_pm[b * MAXNC + c] = mblk; g_pl[b * MAXNC + c] = lblk; }
}

// ---------------------------------------------------------------------------
// Kernel 3: combine chunk partials.  grid(B), 256 threads (k and k+256).
// ---------------------------------------------------------------------------
__global__ void __launch_bounds__(256) k3_combine(float* __restrict__ out) {
    const int b   = blockIdx.x;
    const int tid = threadIdx.x;
    const int n   = (b < NB14) ? 14 : 13;

    __shared__ float spm[MAXNC], spl[MAXNC];
    if (tid < n) { spm[tid] = g_pm[b * MAXNC + tid]; spl[tid] = g_pl[b * MAXNC + tid]; }
    __syncthreads();

    float mstar = -1e30f;
    for (int cc = 0; cc < n; ++cc) mstar = fmaxf(mstar, spm[cc]);

    float denom = 0.f, n0 = 0.f, n1 = 0.f;
    for (int cc = 0; cc < n; ++cc) {
        const float fc = __expf(spm[cc] - mstar);
        denom += fc * spl[cc];
        const size_t pbase = ((size_t)b * MAXNC + cc) * KVD;
        n0 += fc * g_pacc[pbase + tid];
        n1 += fc * g_pacc[pbase + tid + 256];
    }
    out[b * KVD + tid]       = n0 / denom;
    out[b * KVD + tid + 256] = n1 / denom;
}

// ---------------------------------------------------------------------------
extern "C" void kernel_launch(void* const* d_in, const int* in_sizes, int n_in,
                              void* d_out, int out_size) {
    const float* query  = (const float*)d_in[0];   // [32, 512]
    const float* kv     = (const float*)d_in[1];   // [32, 4096, 512]
    const int*   mask   = (const int*)  d_in[2];   // [32, 4096]
    const float* weight = (const float*)d_in[3];   // [512, 512]
    float* out = (float*)d_out;                    // [32, 512]

    (void)in_sizes; (void)n_in; (void)out_size;

    k1_wq<<<dim3(QSLICES, B_), 256>>>(query, weight);
    k1r_reduce<<<64, 256>>>();
    k2_fused<<<444, 256>>>(kv, mask);
    k3_combine<<<B_, 256>>>(out);
}